// round 1
// baseline (speedup 1.0000x reference)
#include <cuda_runtime.h>
#include <math.h>

#define NPTS 16384
#define MCTR 4096
#define NIN  64
#define NOUTF 128
#define DIMF 67
#define KNB  64
#define R2   0.25f

#define OFF_POS   (MCTR * NOUTF)          // 524288
#define OFF_BATCH (OFF_POS + MCTR * 3)    // 536576
#define OFF_IDX   (OFF_BATCH + MCTR)      // 540672

// eval-BN scale: float(1.0/sqrt(1.0+1e-5))
#define SFAC 0.9999950000374996f

// ---------------- scratch (device globals: no allocations allowed) ----------
__device__ int g_idx[MCTR];
__device__ int g_nbr[MCTR * KNB];
__device__ int g_cnt[MCTR];

// ---------------- FPS: single persistent block ------------------------------
// 512 threads, 32 points/thread in registers. dmin in dynamic smem (64KB).
// Exact replication of jax scan: idx[0]=0; idx[t]=argmax(dmin) after update
// with pos[idx[t-1]]. No FMA contraction in distance; first-max tie-break.

__device__ __forceinline__ void combine_max(float& v, int& i, float v2, int i2) {
    if (v2 > v || (v2 == v && i2 < i)) { v = v2; i = i2; }
}

__global__ void __launch_bounds__(512, 1) fps_kernel(const float* __restrict__ pos)
{
    extern __shared__ float sdmin[];              // 16384 floats
    __shared__ float s_cur[3];
    __shared__ int   s_last;
    __shared__ float s_wv[16];
    __shared__ int   s_wi[16];

    const int t = threadIdx.x;
    const float INF = __int_as_float(0x7f800000);

    float px[32], py[32], pz[32];
#pragma unroll
    for (int s = 0; s < 32; s++) {
        int i = (s << 9) + t;
        px[s] = pos[i * 3 + 0];
        py[s] = pos[i * 3 + 1];
        pz[s] = pos[i * 3 + 2];
        sdmin[i] = INF;
    }
    if (t == 0) {
        g_idx[0] = 0;
        s_cur[0] = px[0]; s_cur[1] = py[0]; s_cur[2] = pz[0];
    }
    __syncthreads();

    const int warp = t >> 5;
    const int lane = t & 31;

    for (int it = 1; it < MCTR; it++) {
        float cx = s_cur[0], cy = s_cur[1], cz = s_cur[2];

        float best = -INF;
        int   bidx = 0x7FFFFFFF;
#pragma unroll
        for (int s = 0; s < 32; s++) {
            int i = (s << 9) + t;
            float dx = px[s] - cx;
            float dy = py[s] - cy;
            float dz = pz[s] - cz;
            // ((dx*dx + dy*dy) + dz*dz), no contraction
            float d  = __fadd_rn(__fadd_rn(__fmul_rn(dx, dx), __fmul_rn(dy, dy)),
                                 __fmul_rn(dz, dz));
            float old = sdmin[i];
            float nd  = fminf(old, d);
            sdmin[i]  = nd;
            if (nd > best) { best = nd; bidx = i; }  // strict > keeps smaller i
        }
        // warp reduce
#pragma unroll
        for (int o = 16; o > 0; o >>= 1) {
            float v2 = __shfl_down_sync(0xffffffffu, best, o);
            int   i2 = __shfl_down_sync(0xffffffffu, bidx, o);
            combine_max(best, bidx, v2, i2);
        }
        if (lane == 0) { s_wv[warp] = best; s_wi[warp] = bidx; }
        __syncthreads();

        if (warp == 0) {
            float v = (lane < 16) ? s_wv[lane] : -INF;
            int   i = (lane < 16) ? s_wi[lane] : 0x7FFFFFFF;
#pragma unroll
            for (int o = 8; o > 0; o >>= 1) {
                float v2 = __shfl_down_sync(0xffffffffu, v, o);
                int   i2 = __shfl_down_sync(0xffffffffu, i, o);
                combine_max(v, i, v2, i2);
            }
            if (lane == 0) { s_last = i; g_idx[it] = i; }
        }
        __syncthreads();

        int last = s_last;
        if (t == (last & 511)) {
            int s = last >> 9;
            s_cur[0] = px[s]; s_cur[1] = py[s]; s_cur[2] = pz[s];
        }
        __syncthreads();
    }
}

// ---------------- ball query: one block per centroid ------------------------
// Collect candidates (d2 <= R2) into smem as packed (d2bits<<32 | idx) keys,
// bitonic-sort ascending when >64, keep first 64. Set equality with jax top_k.

#define CAND_CAP 2048

__global__ void __launch_bounds__(256) ball_kernel(const float* __restrict__ pos)
{
    __shared__ unsigned long long keys[CAND_CAP];
    __shared__ int s_cnt;

    const int m   = blockIdx.x;
    const int tid = threadIdx.x;

    if (tid == 0) s_cnt = 0;
    __syncthreads();

    int ci = g_idx[m];
    float cx = pos[ci * 3 + 0];
    float cy = pos[ci * 3 + 1];
    float cz = pos[ci * 3 + 2];

    for (int j = tid; j < NPTS; j += 256) {
        float dx = cx - pos[j * 3 + 0];
        float dy = cy - pos[j * 3 + 1];
        float dz = cz - pos[j * 3 + 2];
        float d2 = __fadd_rn(__fadd_rn(__fmul_rn(dx, dx), __fmul_rn(dy, dy)),
                             __fmul_rn(dz, dz));
        if (d2 <= R2) {
            int p = atomicAdd(&s_cnt, 1);
            if (p < CAND_CAP) {
                unsigned long long k =
                    ((unsigned long long)__float_as_uint(d2) << 32) | (unsigned)j;
                keys[p] = k;
            }
        }
    }
    __syncthreads();

    int n = s_cnt;
    if (n > CAND_CAP) n = CAND_CAP;

    if (n > KNB) {
        int npow2 = 128;
        while (npow2 < n) npow2 <<= 1;
        for (int i = n + tid; i < npow2; i += 256)
            keys[i] = 0xFFFFFFFFFFFFFFFFull;
        __syncthreads();
        for (int k2 = 2; k2 <= npow2; k2 <<= 1) {
            for (int j2 = k2 >> 1; j2 > 0; j2 >>= 1) {
                for (int i = tid; i < npow2; i += 256) {
                    int l = i ^ j2;
                    if (l > i) {
                        unsigned long long a = keys[i], b = keys[l];
                        bool up = ((i & k2) == 0);
                        if ((a > b) == up) { keys[i] = b; keys[l] = a; }
                    }
                }
                __syncthreads();
            }
        }
    }

    int cnt = n < KNB ? n : KNB;
    if (tid < cnt)
        g_nbr[m * KNB + tid] = (int)(keys[tid] & 0xFFFFFFFFull);
    if (tid == 0) g_cnt[m] = cnt;
}

// ---------------- PointConv MLP + max-aggregate: one block per centroid -----

#define W1SZ 4492   /* 4489 padded to 16B multiple */
#define W2SZ 8576
#define VECSZ (3*67 + 3*128)
#define HROW 68
#define SMEM_FLOATS (W1SZ + W2SZ + VECSZ + 2*64*HROW)

__global__ void __launch_bounds__(128) mlp_kernel(
    const float* __restrict__ x,   const float* __restrict__ pos,
    const float* __restrict__ w1,  const float* __restrict__ b1,
    const float* __restrict__ g1,  const float* __restrict__ be1,
    const float* __restrict__ w2,  const float* __restrict__ b2,
    const float* __restrict__ g2,  const float* __restrict__ be2,
    float* __restrict__ out)
{
    extern __shared__ float sm[];
    float* sw1  = sm;                 // [67][67], stride 67, 4489 (pad to 4492)
    float* sw2  = sw1 + W1SZ;         // [67][128] 16B-aligned
    float* sb1  = sw2 + W2SZ;
    float* sg1  = sb1 + 67;
    float* sbe1 = sg1 + 67;
    float* sb2  = sbe1 + 67;
    float* sg2  = sb2 + 128;
    float* sbe2 = sg2 + 128;
    float* sh0  = sbe2 + 128;         // [64][68]
    float* sh1  = sh0 + 64 * HROW;    // [64][68]

    __shared__ int   s_nbr[KNB];
    __shared__ float s_ps[3];
    __shared__ int   s_cnt;

    const int tid = threadIdx.x;
    const int m   = blockIdx.x;

    for (int i = tid; i < 4489; i += 128) sw1[i] = w1[i];
    for (int i = tid; i < W2SZ; i += 128) sw2[i] = w2[i];
    if (tid < 67)  { sb1[tid] = b1[tid]; sg1[tid] = g1[tid]; sbe1[tid] = be1[tid]; }
    if (tid < 128) { sb2[tid] = b2[tid]; sg2[tid] = g2[tid]; sbe2[tid] = be2[tid]; }
    if (tid == 0) {
        s_cnt = g_cnt[m];
        int ci = g_idx[m];
        s_ps[0] = pos[ci*3+0]; s_ps[1] = pos[ci*3+1]; s_ps[2] = pos[ci*3+2];
    }
    __syncthreads();

    const int cnt = s_cnt;
    if (tid < cnt) s_nbr[tid] = g_nbr[m * KNB + tid];
    __syncthreads();

    // build h0 = [x_j, pos_j - pos_i]
    for (int e = tid; e < cnt * NIN; e += 128) {
        int r = e >> 6, c = e & 63;
        sh0[r * HROW + c] = x[s_nbr[r] * NIN + c];
    }
    for (int e = tid; e < cnt * 3; e += 128) {
        int r = e / 3, c = e - 3 * r;
        sh0[r * HROW + 64 + c] = pos[s_nbr[r] * 3 + c] - s_ps[c];
    }
    __syncthreads();

    const int r    = tid >> 1;
    const int half = tid & 1;
    const int c0   = half * 34;     // cols [0,34) / [34,67)

    // layer 1: h1 = bn(relu(h0 @ w1 + b1))
    if (r < cnt) {
        float acc[34];
#pragma unroll
        for (int cc = 0; cc < 34; cc++) acc[cc] = 0.f;
        for (int i = 0; i < DIMF; i++) {
            float a = sh0[r * HROW + i];
            const float* wr = &sw1[i * 67 + c0];
#pragma unroll
            for (int cc = 0; cc < 34; cc++)
                if (c0 + cc < 67) acc[cc] = fmaf(a, wr[cc], acc[cc]);
        }
#pragma unroll
        for (int cc = 0; cc < 34; cc++) {
            int c = c0 + cc;
            if (c < 67) {
                float v = acc[cc] + sb1[c];
                v = fmaxf(v, 0.f);
                v = sg1[c] * (v * SFAC) + sbe1[c];
                sh1[r * HROW + c] = v;
            }
        }
    }
    __syncthreads();

    // layer 2: h2 = bn(relu(h1 @ w2 + b2)), kept in regs
    float acc2[64];
    if (r < cnt) {
#pragma unroll
        for (int cc = 0; cc < 64; cc++) acc2[cc] = 0.f;
        for (int i = 0; i < DIMF; i++) {
            float a = sh1[r * HROW + i];
            const float4* wr = reinterpret_cast<const float4*>(&sw2[i * 128 + half * 64]);
#pragma unroll
            for (int q = 0; q < 16; q++) {
                float4 w4 = wr[q];
                acc2[q*4+0] = fmaf(a, w4.x, acc2[q*4+0]);
                acc2[q*4+1] = fmaf(a, w4.y, acc2[q*4+1]);
                acc2[q*4+2] = fmaf(a, w4.z, acc2[q*4+2]);
                acc2[q*4+3] = fmaf(a, w4.w, acc2[q*4+3]);
            }
        }
    }
    __syncthreads();   // all reads of sh1 done; safe to overwrite region below

    float* sred = sh0;  // [64][128] fits in sh0+sh1 (8704 floats)
    if (r < cnt) {
#pragma unroll
        for (int cc = 0; cc < 64; cc++) {
            int c = half * 64 + cc;
            float v = acc2[cc] + sb2[c];
            v = fmaxf(v, 0.f);
            v = sg2[c] * (v * SFAC) + sbe2[c];
            sred[r * 128 + c] = v;
        }
    }
    __syncthreads();

    {
        int c = tid;
        float mv = sred[c];             // cnt >= 1 always (self in ball)
        for (int rr = 1; rr < cnt; rr++)
            mv = fmaxf(mv, sred[rr * 128 + c]);
        out[m * NOUTF + c] = mv;
    }
}

// ---------------- epilogue: pos_s, batch[idx], idx ---------------------------
__global__ void __launch_bounds__(256) epi_kernel(
    const float* __restrict__ pos, const int* __restrict__ batch,
    float* __restrict__ out)
{
    int i = blockIdx.x * 256 + threadIdx.x;
    if (i < MCTR) {
        int j = g_idx[i];
        out[OFF_POS + i * 3 + 0] = pos[j * 3 + 0];
        out[OFF_POS + i * 3 + 1] = pos[j * 3 + 1];
        out[OFF_POS + i * 3 + 2] = pos[j * 3 + 2];
        out[OFF_BATCH + i] = (float)batch[j];
        out[OFF_IDX + i]   = (float)j;
    }
}

// ---------------- launch ------------------------------------------------------
extern "C" void kernel_launch(void* const* d_in, const int* in_sizes, int n_in,
                              void* d_out, int out_size)
{
    const float* x    = (const float*)d_in[0];
    const float* pos  = (const float*)d_in[1];
    const int*   batch= (const int*)  d_in[2];
    const float* w1   = (const float*)d_in[3];
    const float* b1   = (const float*)d_in[4];
    const float* g1   = (const float*)d_in[5];
    const float* be1  = (const float*)d_in[6];
    const float* w2   = (const float*)d_in[7];
    const float* b2   = (const float*)d_in[8];
    const float* g2   = (const float*)d_in[9];
    const float* be2  = (const float*)d_in[10];
    float* out = (float*)d_out;

    cudaFuncSetAttribute(fps_kernel, cudaFuncAttributeMaxDynamicSharedMemorySize,
                         NPTS * (int)sizeof(float));
    cudaFuncSetAttribute(mlp_kernel, cudaFuncAttributeMaxDynamicSharedMemorySize,
                         SMEM_FLOATS * (int)sizeof(float));

    fps_kernel<<<1, 512, NPTS * sizeof(float)>>>(pos);
    ball_kernel<<<MCTR, 256>>>(pos);
    mlp_kernel<<<MCTR, 128, SMEM_FLOATS * sizeof(float)>>>(
        x, pos, w1, b1, g1, be1, w2, b2, g2, be2, out);
    epi_kernel<<<(MCTR + 255) / 256, 256>>>(pos, batch, out);
}

// round 2
// speedup vs baseline: 1.8613x; 1.8613x over previous
#include <cuda_runtime.h>
#include <math.h>
#include <stdint.h>

#define NPTS 16384
#define MCTR 4096
#define NIN  64
#define NOUTF 128
#define DIMF 67
#define KNB  64
#define R2   0.25f

#define OFF_POS   (MCTR * NOUTF)          // 524288
#define OFF_BATCH (OFF_POS + MCTR * 3)    // 536576
#define OFF_IDX   (OFF_BATCH + MCTR)      // 540672

// eval-BN scale: float(1.0/sqrt(1.0+1e-5))
#define SFAC 0.9999950000374996f

// ---------------- scratch (device globals: no allocations allowed) ----------
__device__ int g_idx[MCTR];
__device__ int g_nbr[MCTR * KNB];
__device__ int g_cnt[MCTR];

// ---------------- FPS: 8-CTA cluster, dmin in registers ---------------------
// 8 CTAs x 512 threads, 4 points/thread in registers. One barrier.cluster per
// iteration; per-CTA best exchanged via DSMEM (double-buffered). Key packing
// (dminBits<<32 | ~idx) makes u64-max == jnp.argmax first-max tie-break.
// Distance arithmetic identical to the verified single-block version.

#define FPS_CTAS 8
#define FPS_THREADS 512
#define FPS_WARPS (FPS_THREADS / 32)
#define PPT 4   /* points per thread: 16384 / (8*512) */

__device__ __forceinline__ uint32_t smem_u32(const void* p) {
    uint32_t a;
    asm("{ .reg .u64 t; cvta.to.shared.u64 t, %1; cvt.u32.u64 %0, t; }"
        : "=r"(a) : "l"(p));
    return a;
}

__device__ __forceinline__ uint32_t ctarank() {
    uint32_t r;
    asm("mov.u32 %0, %%cluster_ctarank;" : "=r"(r));
    return r;
}

__device__ __forceinline__ void st_cluster_u64(uint32_t local_addr, uint32_t rank,
                                               unsigned long long v) {
    asm volatile(
        "{ .reg .u32 ra; mapa.shared::cluster.u32 ra, %0, %1; "
        "st.shared::cluster.u64 [ra], %2; }"
        :: "r"(local_addr), "r"(rank), "l"(v) : "memory");
}

__device__ __forceinline__ void cluster_barrier() {
    asm volatile("barrier.cluster.arrive.aligned;" ::: "memory");
    asm volatile("barrier.cluster.wait.aligned;" ::: "memory");
}

__global__ void __launch_bounds__(FPS_THREADS, 1) __cluster_dims__(FPS_CTAS, 1, 1)
fps_cluster_kernel(const float* __restrict__ pos)
{
    extern __shared__ float sm[];
    float* sx = sm;             // [NPTS]
    float* sy = sx + NPTS;      // [NPTS]
    float* sz = sy + NPTS;      // [NPTS]
    __shared__ unsigned long long s_exch[2][FPS_CTAS];
    __shared__ unsigned long long s_warp[FPS_WARPS];

    const int t    = threadIdx.x;
    const int lane = t & 31;
    const int wid  = t >> 5;
    const uint32_t rank = ctarank();
    const int base = (rank * FPS_THREADS + t) * PPT;   // contiguous 4 pts

    // SoA pos copy into smem (each CTA holds all points)
    for (int i = t; i < NPTS; i += FPS_THREADS) {
        sx[i] = pos[3 * i + 0];
        sy[i] = pos[3 * i + 1];
        sz[i] = pos[3 * i + 2];
    }

    const float INF = __int_as_float(0x7f800000);
    float px[PPT], py[PPT], pz[PPT], dmin[PPT];
#pragma unroll
    for (int k = 0; k < PPT; k++) {
        px[k]   = pos[3 * (base + k) + 0];
        py[k]   = pos[3 * (base + k) + 1];
        pz[k]   = pos[3 * (base + k) + 2];
        dmin[k] = INF;
    }

    float cx = pos[0], cy = pos[1], cz = pos[2];   // centroid 0 = point 0
    if (rank == 0 && t == 0) g_idx[0] = 0;

    __syncthreads();        // smem SoA ready (consumed at winner lookup)

    const uint32_t exch_base = smem_u32(&s_exch[0][0]);
    int par = 0;

    for (int it = 1; it < MCTR; it++) {
        // ---- local compute: update dmin, track (best, idx) with strict > ----
        float bv = -INF;
        int   bi = 0;
#pragma unroll
        for (int k = 0; k < PPT; k++) {
            float dx = __fsub_rn(px[k], cx);
            float dy = __fsub_rn(py[k], cy);
            float dz = __fsub_rn(pz[k], cz);
            float d  = __fadd_rn(__fadd_rn(__fmul_rn(dx, dx), __fmul_rn(dy, dy)),
                                 __fmul_rn(dz, dz));
            float nd = fminf(dmin[k], d);
            dmin[k]  = nd;
            if (nd > bv) { bv = nd; bi = base + k; }   // ascending k => first-max
        }
        unsigned long long key =
            ((unsigned long long)__float_as_uint(bv) << 32) |
            (unsigned)(0xFFFFFFFFu - (unsigned)bi);

        // ---- warp reduce (u64 max == value max, smaller idx on tie) ----
#pragma unroll
        for (int o = 16; o > 0; o >>= 1) {
            unsigned long long k2 = __shfl_down_sync(0xffffffffu, key, o);
            if (k2 > key) key = k2;
        }
        if (lane == 0) s_warp[wid] = key;
        __syncthreads();

        // ---- warp 0: block reduce + DSMEM scatter to all 8 CTAs ----
        if (wid == 0) {
            unsigned long long k = (lane < FPS_WARPS) ? s_warp[lane] : 0ull;
#pragma unroll
            for (int o = 8; o > 0; o >>= 1) {
                unsigned long long k2 = __shfl_xor_sync(0xffffffffu, k, o);
                if (k2 > k) k = k2;
            }
            // all lanes now hold the CTA best; lanes 0..7 fan out to rank=lane
            if (lane < FPS_CTAS) {
                uint32_t slot = exch_base + (uint32_t)(par * FPS_CTAS + rank) * 8u;
                st_cluster_u64(slot, (uint32_t)lane, k);
            }
        }

        cluster_barrier();   // release writes / acquire reads

        // ---- every warp redundantly reduces the 8 CTA candidates ----
        unsigned long long k = (lane < FPS_CTAS) ? s_exch[par][lane] : 0ull;
#pragma unroll
        for (int o = 4; o > 0; o >>= 1) {
            unsigned long long k2 = __shfl_xor_sync(0xffffffffu, k, o);
            if (k2 > k) k = k2;
        }
        k = __shfl_sync(0xffffffffu, k, 0);
        int winner = (int)(0xFFFFFFFFu - (unsigned)k);

        cx = sx[winner]; cy = sy[winner]; cz = sz[winner];   // LDS broadcast
        if (rank == 0 && t == 0) g_idx[it] = winner;
        par ^= 1;
    }
}

// ---------------- ball query: one block per centroid ------------------------

#define CAND_CAP 2048

__global__ void __launch_bounds__(256) ball_kernel(const float* __restrict__ pos)
{
    __shared__ unsigned long long keys[CAND_CAP];
    __shared__ int s_cnt;

    const int m   = blockIdx.x;
    const int tid = threadIdx.x;

    if (tid == 0) s_cnt = 0;
    __syncthreads();

    int ci = g_idx[m];
    float cx = pos[ci * 3 + 0];
    float cy = pos[ci * 3 + 1];
    float cz = pos[ci * 3 + 2];

    for (int j = tid; j < NPTS; j += 256) {
        float dx = cx - pos[j * 3 + 0];
        float dy = cy - pos[j * 3 + 1];
        float dz = cz - pos[j * 3 + 2];
        float d2 = __fadd_rn(__fadd_rn(__fmul_rn(dx, dx), __fmul_rn(dy, dy)),
                             __fmul_rn(dz, dz));
        if (d2 <= R2) {
            int p = atomicAdd(&s_cnt, 1);
            if (p < CAND_CAP) {
                unsigned long long k =
                    ((unsigned long long)__float_as_uint(d2) << 32) | (unsigned)j;
                keys[p] = k;
            }
        }
    }
    __syncthreads();

    int n = s_cnt;
    if (n > CAND_CAP) n = CAND_CAP;

    if (n > KNB) {
        int npow2 = 128;
        while (npow2 < n) npow2 <<= 1;
        for (int i = n + tid; i < npow2; i += 256)
            keys[i] = 0xFFFFFFFFFFFFFFFFull;
        __syncthreads();
        for (int k2 = 2; k2 <= npow2; k2 <<= 1) {
            for (int j2 = k2 >> 1; j2 > 0; j2 >>= 1) {
                for (int i = tid; i < npow2; i += 256) {
                    int l = i ^ j2;
                    if (l > i) {
                        unsigned long long a = keys[i], b = keys[l];
                        bool up = ((i & k2) == 0);
                        if ((a > b) == up) { keys[i] = b; keys[l] = a; }
                    }
                }
                __syncthreads();
            }
        }
    }

    int cnt = n < KNB ? n : KNB;
    if (tid < cnt)
        g_nbr[m * KNB + tid] = (int)(keys[tid] & 0xFFFFFFFFull);
    if (tid == 0) g_cnt[m] = cnt;
}

// ---------------- PointConv MLP + max-aggregate: one block per centroid -----

#define W1SZ 4492   /* 4489 padded to 16B multiple */
#define W2SZ 8576
#define VECSZ (3*67 + 3*128)
#define HROW 68
#define SMEM_FLOATS (W1SZ + W2SZ + VECSZ + 2*64*HROW)

__global__ void __launch_bounds__(128) mlp_kernel(
    const float* __restrict__ x,   const float* __restrict__ pos,
    const float* __restrict__ w1,  const float* __restrict__ b1,
    const float* __restrict__ g1,  const float* __restrict__ be1,
    const float* __restrict__ w2,  const float* __restrict__ b2,
    const float* __restrict__ g2,  const float* __restrict__ be2,
    float* __restrict__ out)
{
    extern __shared__ float sm[];
    float* sw1  = sm;                 // [67][67], stride 67
    float* sw2  = sw1 + W1SZ;         // [67][128]
    float* sb1  = sw2 + W2SZ;
    float* sg1  = sb1 + 67;
    float* sbe1 = sg1 + 67;
    float* sb2  = sbe1 + 67;
    float* sg2  = sb2 + 128;
    float* sbe2 = sg2 + 128;
    float* sh0  = sbe2 + 128;         // [64][68]
    float* sh1  = sh0 + 64 * HROW;    // [64][68]

    __shared__ int   s_nbr[KNB];
    __shared__ float s_ps[3];
    __shared__ int   s_cnt;

    const int tid = threadIdx.x;
    const int m   = blockIdx.x;

    for (int i = tid; i < 4489; i += 128) sw1[i] = w1[i];
    for (int i = tid; i < W2SZ; i += 128) sw2[i] = w2[i];
    if (tid < 67)  { sb1[tid] = b1[tid]; sg1[tid] = g1[tid]; sbe1[tid] = be1[tid]; }
    if (tid < 128) { sb2[tid] = b2[tid]; sg2[tid] = g2[tid]; sbe2[tid] = be2[tid]; }
    if (tid == 0) {
        s_cnt = g_cnt[m];
        int ci = g_idx[m];
        s_ps[0] = pos[ci*3+0]; s_ps[1] = pos[ci*3+1]; s_ps[2] = pos[ci*3+2];
    }
    __syncthreads();

    const int cnt = s_cnt;
    if (tid < cnt) s_nbr[tid] = g_nbr[m * KNB + tid];
    __syncthreads();

    for (int e = tid; e < cnt * NIN; e += 128) {
        int r = e >> 6, c = e & 63;
        sh0[r * HROW + c] = x[s_nbr[r] * NIN + c];
    }
    for (int e = tid; e < cnt * 3; e += 128) {
        int r = e / 3, c = e - 3 * r;
        sh0[r * HROW + 64 + c] = pos[s_nbr[r] * 3 + c] - s_ps[c];
    }
    __syncthreads();

    const int r    = tid >> 1;
    const int half = tid & 1;
    const int c0   = half * 34;

    if (r < cnt) {
        float acc[34];
#pragma unroll
        for (int cc = 0; cc < 34; cc++) acc[cc] = 0.f;
        for (int i = 0; i < DIMF; i++) {
            float a = sh0[r * HROW + i];
            const float* wr = &sw1[i * 67 + c0];
#pragma unroll
            for (int cc = 0; cc < 34; cc++)
                if (c0 + cc < 67) acc[cc] = fmaf(a, wr[cc], acc[cc]);
        }
#pragma unroll
        for (int cc = 0; cc < 34; cc++) {
            int c = c0 + cc;
            if (c < 67) {
                float v = acc[cc] + sb1[c];
                v = fmaxf(v, 0.f);
                v = sg1[c] * (v * SFAC) + sbe1[c];
                sh1[r * HROW + c] = v;
            }
        }
    }
    __syncthreads();

    float acc2[64];
    if (r < cnt) {
#pragma unroll
        for (int cc = 0; cc < 64; cc++) acc2[cc] = 0.f;
        for (int i = 0; i < DIMF; i++) {
            float a = sh1[r * HROW + i];
            const float4* wr = reinterpret_cast<const float4*>(&sw2[i * 128 + half * 64]);
#pragma unroll
            for (int q = 0; q < 16; q++) {
                float4 w4 = wr[q];
                acc2[q*4+0] = fmaf(a, w4.x, acc2[q*4+0]);
                acc2[q*4+1] = fmaf(a, w4.y, acc2[q*4+1]);
                acc2[q*4+2] = fmaf(a, w4.z, acc2[q*4+2]);
                acc2[q*4+3] = fmaf(a, w4.w, acc2[q*4+3]);
            }
        }
    }
    __syncthreads();

    float* sred = sh0;
    if (r < cnt) {
#pragma unroll
        for (int cc = 0; cc < 64; cc++) {
            int c = half * 64 + cc;
            float v = acc2[cc] + sb2[c];
            v = fmaxf(v, 0.f);
            v = sg2[c] * (v * SFAC) + sbe2[c];
            sred[r * 128 + c] = v;
        }
    }
    __syncthreads();

    {
        int c = tid;
        float mv = sred[c];
        for (int rr = 1; rr < cnt; rr++)
            mv = fmaxf(mv, sred[rr * 128 + c]);
        out[m * NOUTF + c] = mv;
    }
}

// ---------------- epilogue ----------------------------------------------------
__global__ void __launch_bounds__(256) epi_kernel(
    const float* __restrict__ pos, const int* __restrict__ batch,
    float* __restrict__ out)
{
    int i = blockIdx.x * 256 + threadIdx.x;
    if (i < MCTR) {
        int j = g_idx[i];
        out[OFF_POS + i * 3 + 0] = pos[j * 3 + 0];
        out[OFF_POS + i * 3 + 1] = pos[j * 3 + 1];
        out[OFF_POS + i * 3 + 2] = pos[j * 3 + 2];
        out[OFF_BATCH + i] = (float)batch[j];
        out[OFF_IDX + i]   = (float)j;
    }
}

// ---------------- launch ------------------------------------------------------
extern "C" void kernel_launch(void* const* d_in, const int* in_sizes, int n_in,
                              void* d_out, int out_size)
{
    const float* x    = (const float*)d_in[0];
    const float* pos  = (const float*)d_in[1];
    const int*   batch= (const int*)  d_in[2];
    const float* w1   = (const float*)d_in[3];
    const float* b1   = (const float*)d_in[4];
    const float* g1   = (const float*)d_in[5];
    const float* be1  = (const float*)d_in[6];
    const float* w2   = (const float*)d_in[7];
    const float* b2   = (const float*)d_in[8];
    const float* g2   = (const float*)d_in[9];
    const float* be2  = (const float*)d_in[10];
    float* out = (float*)d_out;

    cudaFuncSetAttribute(fps_cluster_kernel,
                         cudaFuncAttributeMaxDynamicSharedMemorySize,
                         3 * NPTS * (int)sizeof(float));
    cudaFuncSetAttribute(mlp_kernel, cudaFuncAttributeMaxDynamicSharedMemorySize,
                         SMEM_FLOATS * (int)sizeof(float));

    fps_cluster_kernel<<<FPS_CTAS, FPS_THREADS, 3 * NPTS * sizeof(float)>>>(pos);
    ball_kernel<<<MCTR, 256>>>(pos);
    mlp_kernel<<<MCTR, 128, SMEM_FLOATS * sizeof(float)>>>(
        x, pos, w1, b1, g1, be1, w2, b2, g2, be2, out);
    epi_kernel<<<(MCTR + 255) / 256, 256>>>(pos, batch, out);
}

// round 3
// speedup vs baseline: 1.8987x; 1.0201x over previous
#include <cuda_runtime.h>
#include <math.h>
#include <stdint.h>

#define NPTS 16384
#define MCTR 4096
#define NIN  64
#define NOUTF 128
#define DIMF 67
#define KNB  64
#define R2   0.25f

#define OFF_POS   (MCTR * NOUTF)
#define OFF_BATCH (OFF_POS + MCTR * 3)
#define OFF_IDX   (OFF_BATCH + MCTR)

#define SFAC 0.9999950000374996f

__device__ int g_idx[MCTR];
__device__ int g_nbr[MCTR * KNB];
__device__ int g_cnt[MCTR];

// ---------------- FPS: 8-CTA cluster, mbarrier exchange, redux argmax -------

#define FPS_CTAS 8
#define FPS_THREADS 512
#define FPS_WARPS (FPS_THREADS / 32)
#define PPT 4

__device__ __forceinline__ uint32_t smem_u32(const void* p) {
    uint32_t a;
    asm("{ .reg .u64 t; cvta.to.shared.u64 t, %1; cvt.u32.u64 %0, t; }"
        : "=r"(a) : "l"(p));
    return a;
}

__device__ __forceinline__ uint32_t ctarank() {
    uint32_t r;
    asm("mov.u32 %0, %%cluster_ctarank;" : "=r"(r));
    return r;
}

__device__ __forceinline__ void st_cluster_u64(uint32_t local_addr, uint32_t rank,
                                               unsigned long long v) {
    asm volatile(
        "{ .reg .u32 ra; mapa.shared::cluster.u32 ra, %0, %1; "
        "st.shared::cluster.u64 [ra], %2; }"
        :: "r"(local_addr), "r"(rank), "l"(v) : "memory");
}

__device__ __forceinline__ void mbar_arrive_cluster(uint32_t local_mbar, uint32_t rank) {
    asm volatile(
        "{ .reg .u32 ra; mapa.shared::cluster.u32 ra, %0, %1; "
        "mbarrier.arrive.release.cluster.shared::cluster.b64 _, [ra]; }"
        :: "r"(local_mbar), "r"(rank) : "memory");
}

__device__ __forceinline__ void mbar_wait_cluster(uint32_t mbar, uint32_t parity) {
    asm volatile(
        "{\n\t"
        ".reg .pred P;\n\t"
        "W_%=:\n\t"
        "mbarrier.try_wait.parity.acquire.cluster.shared::cta.b64 P, [%0], %1, 0x989680;\n\t"
        "@P bra.uni D_%=;\n\t"
        "bra.uni W_%=;\n\t"
        "D_%=:\n\t"
        "}"
        :: "r"(mbar), "r"(parity) : "memory");
}

__device__ __forceinline__ unsigned redux_max_u32(unsigned v) {
    unsigned r;
    asm volatile("redux.sync.max.u32 %0, %1, 0xffffffff;" : "=r"(r) : "r"(v));
    return r;
}

// warp argmax: max val, smallest-lane idx on ties (lanes ordered by global idx)
__device__ __forceinline__ void warp_argmax(unsigned& val, int& idx, unsigned amask) {
    unsigned m = redux_max_u32(val);
    unsigned b = __ballot_sync(0xffffffffu, val == m) & amask;
    int src = __ffs(b) - 1;
    idx = __shfl_sync(0xffffffffu, idx, src);
    val = m;
}

__global__ void __launch_bounds__(FPS_THREADS, 1) __cluster_dims__(FPS_CTAS, 1, 1)
fps_cluster_kernel(const float* __restrict__ pos)
{
    extern __shared__ float sm[];
    float* sx = sm;
    float* sy = sx + NPTS;
    float* sz = sy + NPTS;
    __shared__ unsigned long long s_slot[2][FPS_CTAS];
    __shared__ unsigned s_wval[FPS_WARPS];
    __shared__ int      s_widx[FPS_WARPS];
    __shared__ unsigned long long s_mbar;

    const int t    = threadIdx.x;
    const int lane = t & 31;
    const int wid  = t >> 5;
    const uint32_t rank = ctarank();
    const int base = (rank * FPS_THREADS + t) * PPT;

    for (int i = t; i < NPTS; i += FPS_THREADS) {
        sx[i] = pos[3 * i + 0];
        sy[i] = pos[3 * i + 1];
        sz[i] = pos[3 * i + 2];
    }

    const float INF = __int_as_float(0x7f800000);
    float px[PPT], py[PPT], pz[PPT], dmin[PPT];
#pragma unroll
    for (int k = 0; k < PPT; k++) {
        px[k]   = pos[3 * (base + k) + 0];
        py[k]   = pos[3 * (base + k) + 1];
        pz[k]   = pos[3 * (base + k) + 2];
        dmin[k] = INF;
    }

    float cx = pos[0], cy = pos[1], cz = pos[2];
    if (rank == 0 && t == 0) g_idx[0] = 0;

    const uint32_t mbar = smem_u32(&s_mbar);
    const uint32_t slot0 = smem_u32(&s_slot[0][0]);
    if (t == 0)
        asm volatile("mbarrier.init.shared.b64 [%0], %1;"
                     :: "r"(mbar), "r"(FPS_CTAS) : "memory");
    __syncthreads();
    // all CTAs: mbarriers init'd + SoA ready before any remote traffic
    asm volatile("barrier.cluster.arrive.aligned;" ::: "memory");
    asm volatile("barrier.cluster.wait.aligned;" ::: "memory");

    unsigned par = 0;

    for (int it = 1; it < MCTR; it++) {
        // ---- local dmin update + per-thread argmax (ascending k: first-max) --
        float bvf = -INF;
        int   bi  = base;
#pragma unroll
        for (int k = 0; k < PPT; k++) {
            float dx = __fsub_rn(px[k], cx);
            float dy = __fsub_rn(py[k], cy);
            float dz = __fsub_rn(pz[k], cz);
            float d  = __fadd_rn(__fadd_rn(__fmul_rn(dx, dx), __fmul_rn(dy, dy)),
                                 __fmul_rn(dz, dz));
            float nd = fminf(dmin[k], d);
            dmin[k]  = nd;
            if (nd > bvf) { bvf = nd; bi = base + k; }
        }
        unsigned bv = __float_as_uint(fmaxf(bvf, 0.0f));  // dmin >= 0; keep u32 order
        int      bx = bi;

        warp_argmax(bv, bx, 0xffffffffu);
        if (lane == 0) { s_wval[wid] = bv; s_widx[wid] = bx; }
        __syncthreads();

        if (wid == 0) {
            unsigned v = (lane < FPS_WARPS) ? s_wval[lane] : 0u;
            int      i = (lane < FPS_WARPS) ? s_widx[lane] : 0;
            warp_argmax(v, i, 0xffffu);
            if (lane < FPS_CTAS) {
                unsigned long long key =
                    ((unsigned long long)v << 32) | (unsigned)i;
                uint32_t slot = slot0 + (uint32_t)(par * FPS_CTAS + rank) * 8u;
                st_cluster_u64(slot, (uint32_t)lane, key);
                mbar_arrive_cluster(mbar, (uint32_t)lane);
            }
        }

        mbar_wait_cluster(mbar, par);

        // every warp redundantly reduces the 8 CTA candidates
        unsigned long long kk = s_slot[par][lane & 7];
        unsigned v = (lane < FPS_CTAS) ? (unsigned)(kk >> 32) : 0u;
        int      i = (lane < FPS_CTAS) ? (int)(unsigned)kk : 0;
        warp_argmax(v, i, 0xffu);
        int winner = i;

        cx = sx[winner]; cy = sy[winner]; cz = sz[winner];
        if (rank == 0 && t == 0) g_idx[it] = winner;
        par ^= 1;
    }
}

// ---------------- ball query ------------------------------------------------

#define CAND_CAP 2048

__global__ void __launch_bounds__(256) ball_kernel(const float* __restrict__ pos)
{
    __shared__ unsigned long long keys[CAND_CAP];
    __shared__ int s_cnt;

    const int m   = blockIdx.x;
    const int tid = threadIdx.x;

    if (tid == 0) s_cnt = 0;
    __syncthreads();

    int ci = g_idx[m];
    float cx = pos[ci * 3 + 0];
    float cy = pos[ci * 3 + 1];
    float cz = pos[ci * 3 + 2];

    for (int j = tid; j < NPTS; j += 256) {
        float dx = cx - pos[j * 3 + 0];
        float dy = cy - pos[j * 3 + 1];
        float dz = cz - pos[j * 3 + 2];
        float d2 = __fadd_rn(__fadd_rn(__fmul_rn(dx, dx), __fmul_rn(dy, dy)),
                             __fmul_rn(dz, dz));
        if (d2 <= R2) {
            int p = atomicAdd(&s_cnt, 1);
            if (p < CAND_CAP) {
                unsigned long long k =
                    ((unsigned long long)__float_as_uint(d2) << 32) | (unsigned)j;
                keys[p] = k;
            }
        }
    }
    __syncthreads();

    int n = s_cnt;
    if (n > CAND_CAP) n = CAND_CAP;

    if (n > KNB) {
        int npow2 = 128;
        while (npow2 < n) npow2 <<= 1;
        for (int i = n + tid; i < npow2; i += 256)
            keys[i] = 0xFFFFFFFFFFFFFFFFull;
        __syncthreads();
        for (int k2 = 2; k2 <= npow2; k2 <<= 1) {
            for (int j2 = k2 >> 1; j2 > 0; j2 >>= 1) {
                for (int i = tid; i < npow2; i += 256) {
                    int l = i ^ j2;
                    if (l > i) {
                        unsigned long long a = keys[i], b = keys[l];
                        bool up = ((i & k2) == 0);
                        if ((a > b) == up) { keys[i] = b; keys[l] = a; }
                    }
                }
                __syncthreads();
            }
        }
    }

    int cnt = n < KNB ? n : KNB;
    if (tid < cnt)
        g_nbr[m * KNB + tid] = (int)(keys[tid] & 0xFFFFFFFFull);
    if (tid == 0) g_cnt[m] = cnt;
}

// ---------------- PointConv MLP + max-aggregate ------------------------------

#define W1SZ 4492
#define W2SZ 8576
#define VECSZ (3*67 + 3*128)
#define HROW 68
#define SMEM_FLOATS (W1SZ + W2SZ + VECSZ + 2*64*HROW)

__global__ void __launch_bounds__(128) mlp_kernel(
    const float* __restrict__ x,   const float* __restrict__ pos,
    const float* __restrict__ w1,  const float* __restrict__ b1,
    const float* __restrict__ g1,  const float* __restrict__ be1,
    const float* __restrict__ w2,  const float* __restrict__ b2,
    const float* __restrict__ g2,  const float* __restrict__ be2,
    float* __restrict__ out)
{
    extern __shared__ float sm[];
    float* sw1  = sm;
    float* sw2  = sw1 + W1SZ;
    float* sb1  = sw2 + W2SZ;
    float* sg1  = sb1 + 67;
    float* sbe1 = sg1 + 67;
    float* sb2  = sbe1 + 67;
    float* sg2  = sb2 + 128;
    float* sbe2 = sg2 + 128;
    float* sh0  = sbe2 + 128;
    float* sh1  = sh0 + 64 * HROW;

    __shared__ int   s_nbr[KNB];
    __shared__ float s_ps[3];
    __shared__ int   s_cnt;

    const int tid = threadIdx.x;
    const int m   = blockIdx.x;

    for (int i = tid; i < 4489; i += 128) sw1[i] = w1[i];
    for (int i = tid; i < W2SZ; i += 128) sw2[i] = w2[i];
    if (tid < 67)  { sb1[tid] = b1[tid]; sg1[tid] = g1[tid]; sbe1[tid] = be1[tid]; }
    if (tid < 128) { sb2[tid] = b2[tid]; sg2[tid] = g2[tid]; sbe2[tid] = be2[tid]; }
    if (tid == 0) {
        s_cnt = g_cnt[m];
        int ci = g_idx[m];
        s_ps[0] = pos[ci*3+0]; s_ps[1] = pos[ci*3+1]; s_ps[2] = pos[ci*3+2];
    }
    __syncthreads();

    const int cnt = s_cnt;
    if (tid < cnt) s_nbr[tid] = g_nbr[m * KNB + tid];
    __syncthreads();

    for (int e = tid; e < cnt * NIN; e += 128) {
        int r = e >> 6, c = e & 63;
        sh0[r * HROW + c] = x[s_nbr[r] * NIN + c];
    }
    for (int e = tid; e < cnt * 3; e += 128) {
        int r = e / 3, c = e - 3 * r;
        sh0[r * HROW + 64 + c] = pos[s_nbr[r] * 3 + c] - s_ps[c];
    }
    __syncthreads();

    const int r    = tid >> 1;
    const int half = tid & 1;
    const int c0   = half * 34;

    if (r < cnt) {
        float acc[34];
#pragma unroll
        for (int cc = 0; cc < 34; cc++) acc[cc] = 0.f;
        for (int i = 0; i < DIMF; i++) {
            float a = sh0[r * HROW + i];
            const float* wr = &sw1[i * 67 + c0];
#pragma unroll
            for (int cc = 0; cc < 34; cc++)
                if (c0 + cc < 67) acc[cc] = fmaf(a, wr[cc], acc[cc]);
        }
#pragma unroll
        for (int cc = 0; cc < 34; cc++) {
            int c = c0 + cc;
            if (c < 67) {
                float v = acc[cc] + sb1[c];
                v = fmaxf(v, 0.f);
                v = sg1[c] * (v * SFAC) + sbe1[c];
                sh1[r * HROW + c] = v;
            }
        }
    }
    __syncthreads();

    float acc2[64];
    if (r < cnt) {
#pragma unroll
        for (int cc = 0; cc < 64; cc++) acc2[cc] = 0.f;
        for (int i = 0; i < DIMF; i++) {
            float a = sh1[r * HROW + i];
            const float4* wr = reinterpret_cast<const float4*>(&sw2[i * 128 + half * 64]);
#pragma unroll
            for (int q = 0; q < 16; q++) {
                float4 w4 = wr[q];
                acc2[q*4+0] = fmaf(a, w4.x, acc2[q*4+0]);
                acc2[q*4+1] = fmaf(a, w4.y, acc2[q*4+1]);
                acc2[q*4+2] = fmaf(a, w4.z, acc2[q*4+2]);
                acc2[q*4+3] = fmaf(a, w4.w, acc2[q*4+3]);
            }
        }
    }
    __syncthreads();

    float* sred = sh0;
    if (r < cnt) {
#pragma unroll
        for (int cc = 0; cc < 64; cc++) {
            int c = half * 64 + cc;
            float v = acc2[cc] + sb2[c];
            v = fmaxf(v, 0.f);
            v = sg2[c] * (v * SFAC) + sbe2[c];
            sred[r * 128 + c] = v;
        }
    }
    __syncthreads();

    {
        int c = tid;
        float mv = sred[c];
        for (int rr = 1; rr < cnt; rr++)
            mv = fmaxf(mv, sred[rr * 128 + c]);
        out[m * NOUTF + c] = mv;
    }
}

// ---------------- epilogue ----------------------------------------------------
__global__ void __launch_bounds__(256) epi_kernel(
    const float* __restrict__ pos, const int* __restrict__ batch,
    float* __restrict__ out)
{
    int i = blockIdx.x * 256 + threadIdx.x;
    if (i < MCTR) {
        int j = g_idx[i];
        out[OFF_POS + i * 3 + 0] = pos[j * 3 + 0];
        out[OFF_POS + i * 3 + 1] = pos[j * 3 + 1];
        out[OFF_POS + i * 3 + 2] = pos[j * 3 + 2];
        out[OFF_BATCH + i] = (float)batch[j];
        out[OFF_IDX + i]   = (float)j;
    }
}

// ---------------- launch ------------------------------------------------------
extern "C" void kernel_launch(void* const* d_in, const int* in_sizes, int n_in,
                              void* d_out, int out_size)
{
    const float* x    = (const float*)d_in[0];
    const float* pos  = (const float*)d_in[1];
    const int*   batch= (const int*)  d_in[2];
    const float* w1   = (const float*)d_in[3];
    const float* b1   = (const float*)d_in[4];
    const float* g1   = (const float*)d_in[5];
    const float* be1  = (const float*)d_in[6];
    const float* w2   = (const float*)d_in[7];
    const float* b2   = (const float*)d_in[8];
    const float* g2   = (const float*)d_in[9];
    const float* be2  = (const float*)d_in[10];
    float* out = (float*)d_out;

    cudaFuncSetAttribute(fps_cluster_kernel,
                         cudaFuncAttributeMaxDynamicSharedMemorySize,
                         3 * NPTS * (int)sizeof(float));
    cudaFuncSetAttribute(mlp_kernel, cudaFuncAttributeMaxDynamicSharedMemorySize,
                         SMEM_FLOATS * (int)sizeof(float));

    fps_cluster_kernel<<<FPS_CTAS, FPS_THREADS, 3 * NPTS * sizeof(float)>>>(pos);
    ball_kernel<<<MCTR, 256>>>(pos);
    mlp_kernel<<<MCTR, 128, SMEM_FLOATS * sizeof(float)>>>(
        x, pos, w1, b1, g1, be1, w2, b2, g2, be2, out);
    epi_kernel<<<(MCTR + 255) / 256, 256>>>(pos, batch, out);
}